// round 14
// baseline (speedup 1.0000x reference)
#include <cuda_runtime.h>
#include <cuda_fp16.h>
#include <cstdint>

// Problem constants
#define K_TOTAL 4096
#define N_TOTAL 11008
#define M_TOTAL 8192
#define NGROUPS 704512

// Scratch (static device globals)
__device__ __half g_W[(size_t)N_TOTAL * K_TOTAL];   // dequantized fp16, [out][in] K-major
__device__ __half g_x[(size_t)M_TOTAL * K_TOTAL];   // fp16 activations

// ---------------------------------------------------------------------------
// Kernel 1: merged prep (unchanged).
// ---------------------------------------------------------------------------
#define DQ_BLOCKS 22016     // (32*NGROUPS/4) / 256
#define CX_BLOCKS 16384     // (M*K/8) / 256

__global__ void prep_kernel(const int4* __restrict__ Wq,
                            const float4* __restrict__ scale,
                            const float4* __restrict__ zero,
                            const float4* __restrict__ x) {
    int b = blockIdx.x;
    if (b < DQ_BLOCKS) {
        const int total = 32 * NGROUPS;
        int i = b * blockDim.x + threadIdx.x;    // quad index
        int base = i * 4;
        if (base >= total) return;
        int g4 = base % NGROUPS;
        int4 q = Wq[i];
        float4 s = scale[g4 >> 2];
        float4 z = zero[g4 >> 2];

        float h0 = ((float)((q.x >> 4) & 0xF) - z.x) * s.x;
        float l0 = ((float)(q.x & 0xF)        - z.x) * s.x;
        float h1 = ((float)((q.y >> 4) & 0xF) - z.y) * s.y;
        float l1 = ((float)(q.y & 0xF)        - z.y) * s.y;
        float h2 = ((float)((q.z >> 4) & 0xF) - z.z) * s.z;
        float l2 = ((float)(q.z & 0xF)        - z.z) * s.z;
        float h3 = ((float)((q.w >> 4) & 0xF) - z.w) * s.w;
        float l3 = ((float)(q.w & 0xF)        - z.w) * s.w;

        __half2 hA = __floats2half2_rn(h0, h1), hB = __floats2half2_rn(h2, h3);
        __half2 lA = __floats2half2_rn(l0, l1), lB = __floats2half2_rn(l2, l3);
        uint2 hs, ls;
        hs.x = *reinterpret_cast<uint32_t*>(&hA); hs.y = *reinterpret_cast<uint32_t*>(&hB);
        ls.x = *reinterpret_cast<uint32_t*>(&lA); ls.y = *reinterpret_cast<uint32_t*>(&lB);
        *reinterpret_cast<uint2*>(g_W + base)         = hs;
        *reinterpret_cast<uint2*>(g_W + base + total) = ls;
    } else {
        int i = (b - DQ_BLOCKS) * blockDim.x + threadIdx.x;
        const int n8 = (M_TOTAL * K_TOTAL) / 8;
        if (i >= n8) return;
        float4 v0 = x[2 * i];
        float4 v1 = x[2 * i + 1];
        __half2 a = __floats2half2_rn(v0.x, v0.y);
        __half2 bb = __floats2half2_rn(v0.z, v0.w);
        __half2 c = __floats2half2_rn(v1.x, v1.y);
        __half2 d = __floats2half2_rn(v1.z, v1.w);
        uint4 o;
        o.x = *reinterpret_cast<uint32_t*>(&a);
        o.y = *reinterpret_cast<uint32_t*>(&bb);
        o.z = *reinterpret_cast<uint32_t*>(&c);
        o.w = *reinterpret_cast<uint32_t*>(&d);
        reinterpret_cast<uint4*>(g_x)[i] = o;
    }
}

// ---------------------------------------------------------------------------
// Kernel 2: fp16 tensor-core GEMM (mma.sync m16n8k16, fp32 accum).
// Block tile 256(M)x128(N)x64, 8 warps as 4Mx2N — warp tile 64x64 (identical
// per-warp machinery to R13: full A+B fragment double-buffering, 4 LDSM each).
// Per 2048 tensor-cyc of work: crossbar 176KB (69% ratio, was 75%) and ONE
// barrier (was two). 3-stage cp.async pipeline (144KB), 1 CTA/SM, 256 thr
// (reg cap 256 — same budget as R13's 128thr x 2CTA).
// ---------------------------------------------------------------------------
#define BK 64
#define A_BYTES 32768                 // 256 rows x 128B
#define B_BYTES 16384                 // 128 rows x 128B
#define STAGE_BYTES (A_BYTES + B_BYTES)      // 49152
#define NSTAGE 3
#define SMEM_TOTAL (NSTAGE * STAGE_BYTES)    // 147456

#define CP_ASYNC16(dst, src) \
    asm volatile("cp.async.cg.shared.global [%0], [%1], 16;" :: "r"(dst), "l"(src))
#define CP_COMMIT() asm volatile("cp.async.commit_group;" ::: "memory")
#define CP_WAIT(n)  asm volatile("cp.async.wait_group %0;" :: "n"(n) : "memory")

#define LDSM_X4(r0, r1, r2, r3, a)                                            \
    asm volatile("ldmatrix.sync.aligned.m8n8.x4.shared.b16 {%0,%1,%2,%3}, [%4];" \
                 : "=r"(r0), "=r"(r1), "=r"(r2), "=r"(r3) : "r"(a))

__global__ void __launch_bounds__(256, 1)
gemm_fp16_kernel(const float* __restrict__ bias, float* __restrict__ C) {
    extern __shared__ char smem[];
    uint32_t sbase;
    asm("{ .reg .u64 t; cvta.to.shared.u64 t, %1; cvt.u32.u64 %0, t; }"
        : "=r"(sbase) : "l"(smem));

    const int tid  = threadIdx.x;
    const int lane = tid & 31;
    const int warp = tid >> 5;       // 0..7
    const int wm   = warp & 3;       // 4 warps along M (64 rows each)
    const int wn   = warp >> 2;      // 2 warps along N (64 cols each)
    const int gID  = lane >> 2;
    const int t4   = lane & 3;

    // CTA raster: stripes of 16 M-tiles (tiles_m=32 -> exactly 2 stripes).
    const int tiles_n = N_TOTAL / 128;   // 86
    const int GRP = 16;
    int gid = blockIdx.x;
    int stripe = gid / (GRP * tiles_n);
    int rem = gid - stripe * (GRP * tiles_n);
    int tm = stripe * GRP + (rem % GRP);
    int tn = rem / GRP;
    const int m0 = tm * 256;
    const int n0 = tn * 128;

    const __half* Ag = g_x + (size_t)m0 * K_TOTAL;
    const __half* Bg = g_W + (size_t)n0 * K_TOTAL;

    float acc[4][8][4];
#pragma unroll
    for (int i = 0; i < 4; i++)
#pragma unroll
        for (int j = 0; j < 8; j++)
#pragma unroll
            for (int k = 0; k < 4; k++) acc[i][j][k] = 0.f;

    // Per-thread cp.async addressing (256 threads)
    const int crow = tid >> 3;           // 0..31
    const int ccc  = tid & 7;            // chunk
    const uint32_t cdst_off = (uint32_t)crow * 128 + (uint32_t)((ccc ^ (crow & 7)) << 4);

    auto issueA = [&](int kt, int stage) {
        int kbase = kt * BK;
        uint32_t stg = sbase + stage * STAGE_BYTES;
#pragma unroll
        for (int t = 0; t < 8; t++) {            // A: 256 rows x 8 chunks
            uint32_t dst = stg + t * 4096 + cdst_off;
            const __half* src = Ag + (size_t)(t * 32 + crow) * K_TOTAL + kbase + ccc * 8;
            CP_ASYNC16(dst, src);
        }
    };
    auto issueB = [&](int kt, int stage) {
        int kbase = kt * BK;
        uint32_t stg = sbase + stage * STAGE_BYTES + A_BYTES;
#pragma unroll
        for (int t = 0; t < 4; t++) {            // B: 128 rows x 8 chunks
            uint32_t dst = stg + t * 4096 + cdst_off;
            const __half* src = Bg + (size_t)(t * 32 + crow) * K_TOTAL + kbase + ccc * 8;
            CP_ASYNC16(dst, src);
        }
    };

    // ldmatrix per-thread row/chunk decomposition
    const int arow = (lane & 7) + ((lane >> 3) & 1) * 8;   // 0..15
    const int akp  = lane >> 4;                            // 0/1 (k half)
    const int brow = (lane & 7) + (lane >> 4) * 8;         // 0..15
    const int bkp  = (lane >> 3) & 1;                      // 0/1 (k half)
    const int l7   = lane & 7;

    const uint32_t a_row_off = (uint32_t)(wm * 64 + arow) * 128;
    const uint32_t b_row_off = (uint32_t)A_BYTES + (uint32_t)(wn * 64 + brow) * 128;

    // Full double-buffered fragments (reg budget 256/thread at 1 CTA/SM)
    uint32_t afr[2][4][4], bfr[2][4][4];

    auto ldfragA = [&](uint32_t stg, int ks, int buf) {
#pragma unroll
        for (int mt = 0; mt < 4; mt++) {
            uint32_t addr = stg + a_row_off + (uint32_t)(mt * 16) * 128 +
                            (uint32_t)(((2 * ks + akp) ^ l7) << 4);
            LDSM_X4(afr[buf][mt][0], afr[buf][mt][1],
                    afr[buf][mt][2], afr[buf][mt][3], addr);
        }
    };
    auto ldfragB = [&](uint32_t stg, int ks, int buf) {
#pragma unroll
        for (int p = 0; p < 4; p++) {            // 4 LDSM.x4 cover 64 cols
            uint32_t addr = stg + b_row_off + (uint32_t)(p * 16) * 128 +
                            (uint32_t)(((2 * ks + bkp) ^ l7) << 4);
            LDSM_X4(bfr[buf][p][0], bfr[buf][p][1],
                    bfr[buf][p][2], bfr[buf][p][3], addr);
        }
    };

    const int NK = K_TOTAL / BK;   // 64

    issueA(0, 0); issueB(0, 0); CP_COMMIT();
    issueA(1, 1); issueB(1, 1); CP_COMMIT();

    int stage = 0;
    for (int kt = 0; kt < NK; kt++) {
        CP_WAIT(1);
        __syncthreads();
        int s2 = stage + 2; if (s2 >= NSTAGE) s2 -= NSTAGE;
        const bool pf = (kt + 2 < NK);
        uint32_t stg = sbase + stage * STAGE_BYTES;

        // Prime ks=0 fragments (only exposed LDS latency in the stage).
        ldfragA(stg, 0, 0);
        ldfragB(stg, 0, 0);

#pragma unroll
        for (int ks = 0; ks < 4; ks++) {
            const int cur = ks & 1;
            const int nxt = cur ^ 1;
            // Next sub-step's fragments: latency hides under 32 MMAs.
            if (ks < 3) { ldfragA(stg, ks + 1, nxt); ldfragB(stg, ks + 1, nxt); }
#pragma unroll
            for (int mt = 0; mt < 4; mt++)
#pragma unroll
                for (int nt = 0; nt < 8; nt++) {
                    uint32_t b0 = bfr[cur][nt >> 1][(nt & 1) * 2];
                    uint32_t b1 = bfr[cur][nt >> 1][(nt & 1) * 2 + 1];
                    asm volatile(
                        "mma.sync.aligned.m16n8k16.row.col.f32.f16.f16.f32 "
                        "{%0,%1,%2,%3}, {%4,%5,%6,%7}, {%8,%9}, {%0,%1,%2,%3};\n"
                        : "+f"(acc[mt][nt][0]), "+f"(acc[mt][nt][1]),
                          "+f"(acc[mt][nt][2]), "+f"(acc[mt][nt][3])
                        : "r"(afr[cur][mt][0]), "r"(afr[cur][mt][1]),
                          "r"(afr[cur][mt][2]), "r"(afr[cur][mt][3]),
                          "r"(b0), "r"(b1));
                }
            // Interleave next-stage global prefetch into the MMA stream.
            if (ks == 0 && pf) issueA(kt + 2, s2);
            if (ks == 1) { if (pf) issueB(kt + 2, s2); CP_COMMIT(); }
        }
        stage = (stage + 1 == NSTAGE) ? 0 : stage + 1;
    }

    // Epilogue: bias add + fp32 stores
    float2 bv[8];
#pragma unroll
    for (int nt = 0; nt < 8; nt++) {
        int col = n0 + wn * 64 + nt * 8 + t4 * 2;
        bv[nt] = *reinterpret_cast<const float2*>(bias + col);
    }
#pragma unroll
    for (int mt = 0; mt < 4; mt++) {
#pragma unroll
        for (int nt = 0; nt < 8; nt++) {
            int row0 = m0 + wm * 64 + mt * 16 + gID;
            int col  = n0 + wn * 64 + nt * 8 + t4 * 2;
            float2 v0 = make_float2(acc[mt][nt][0] + bv[nt].x, acc[mt][nt][1] + bv[nt].y);
            float2 v1 = make_float2(acc[mt][nt][2] + bv[nt].x, acc[mt][nt][3] + bv[nt].y);
            *reinterpret_cast<float2*>(C + (size_t)row0 * N_TOTAL + col)       = v0;
            *reinterpret_cast<float2*>(C + (size_t)(row0 + 8) * N_TOTAL + col) = v1;
        }
    }
}

// ---------------------------------------------------------------------------
// Launch. Inputs: x, W_q, scale, zero, bias. Output fp32.
// ---------------------------------------------------------------------------
extern "C" void kernel_launch(void* const* d_in, const int* in_sizes, int n_in,
                              void* d_out, int out_size) {
    const float* x     = (const float*)d_in[0];
    const int*   Wq    = (const int*)d_in[1];
    const float* scale = (const float*)d_in[2];
    const float* zero  = (const float*)d_in[3];
    const float* bias  = (const float*)d_in[4];
    float* out = (float*)d_out;

    prep_kernel<<<DQ_BLOCKS + CX_BLOCKS, 256>>>((const int4*)Wq,
                                                (const float4*)scale,
                                                (const float4*)zero,
                                                (const float4*)x);
    {
        cudaFuncSetAttribute(gemm_fp16_kernel,
                             cudaFuncAttributeMaxDynamicSharedMemorySize, SMEM_TOTAL);
        int blocks = (M_TOTAL / 256) * (N_TOTAL / 128);   // 32 * 86 = 2752
        gemm_fp16_kernel<<<blocks, 256, SMEM_TOTAL>>>(bias, out);
    }
}

// round 15
// speedup vs baseline: 1.0693x; 1.0693x over previous
#include <cuda_runtime.h>
#include <cuda_fp16.h>
#include <cstdint>

// Problem constants
#define K_TOTAL 4096
#define N_TOTAL 11008
#define M_TOTAL 8192
#define NGROUPS 704512

// Scratch (static device globals)
__device__ __half g_W[(size_t)N_TOTAL * K_TOTAL];   // dequantized fp16, [out][in] K-major
__device__ __half g_x[(size_t)M_TOTAL * K_TOTAL];   // fp16 activations

// ---------------------------------------------------------------------------
// Kernel 1: merged prep (unchanged).
// ---------------------------------------------------------------------------
#define DQ_BLOCKS 22016     // (32*NGROUPS/4) / 256
#define CX_BLOCKS 16384     // (M*K/8) / 256

__global__ void prep_kernel(const int4* __restrict__ Wq,
                            const float4* __restrict__ scale,
                            const float4* __restrict__ zero,
                            const float4* __restrict__ x) {
    int b = blockIdx.x;
    if (b < DQ_BLOCKS) {
        const int total = 32 * NGROUPS;
        int i = b * blockDim.x + threadIdx.x;    // quad index
        int base = i * 4;
        if (base >= total) return;
        int g4 = base % NGROUPS;
        int4 q = Wq[i];
        float4 s = scale[g4 >> 2];
        float4 z = zero[g4 >> 2];

        float h0 = ((float)((q.x >> 4) & 0xF) - z.x) * s.x;
        float l0 = ((float)(q.x & 0xF)        - z.x) * s.x;
        float h1 = ((float)((q.y >> 4) & 0xF) - z.y) * s.y;
        float l1 = ((float)(q.y & 0xF)        - z.y) * s.y;
        float h2 = ((float)((q.z >> 4) & 0xF) - z.z) * s.z;
        float l2 = ((float)(q.z & 0xF)        - z.z) * s.z;
        float h3 = ((float)((q.w >> 4) & 0xF) - z.w) * s.w;
        float l3 = ((float)(q.w & 0xF)        - z.w) * s.w;

        __half2 hA = __floats2half2_rn(h0, h1), hB = __floats2half2_rn(h2, h3);
        __half2 lA = __floats2half2_rn(l0, l1), lB = __floats2half2_rn(l2, l3);
        uint2 hs, ls;
        hs.x = *reinterpret_cast<uint32_t*>(&hA); hs.y = *reinterpret_cast<uint32_t*>(&hB);
        ls.x = *reinterpret_cast<uint32_t*>(&lA); ls.y = *reinterpret_cast<uint32_t*>(&lB);
        *reinterpret_cast<uint2*>(g_W + base)         = hs;
        *reinterpret_cast<uint2*>(g_W + base + total) = ls;
    } else {
        int i = (b - DQ_BLOCKS) * blockDim.x + threadIdx.x;
        const int n8 = (M_TOTAL * K_TOTAL) / 8;
        if (i >= n8) return;
        float4 v0 = x[2 * i];
        float4 v1 = x[2 * i + 1];
        __half2 a = __floats2half2_rn(v0.x, v0.y);
        __half2 bb = __floats2half2_rn(v0.z, v0.w);
        __half2 c = __floats2half2_rn(v1.x, v1.y);
        __half2 d = __floats2half2_rn(v1.z, v1.w);
        uint4 o;
        o.x = *reinterpret_cast<uint32_t*>(&a);
        o.y = *reinterpret_cast<uint32_t*>(&bb);
        o.z = *reinterpret_cast<uint32_t*>(&c);
        o.w = *reinterpret_cast<uint32_t*>(&d);
        reinterpret_cast<uint4*>(g_x)[i] = o;
    }
}

// ---------------------------------------------------------------------------
// Kernel 2: fp16 tensor-core GEMM — R13 mainloop (block 128x128x64, 4 warps
// as 2Mx2N, warp tile 64x64, full A+B fragment double-buffering, 3-stage
// cp.async ring, 2 CTAs/SM) made PERSISTENT with peeled tile transitions:
// the hot kt-loop body is identical to R13 (pf const-folded true); only the
// last two kt iterations per tile are peeled to prefetch the next tile's
// first two K-tiles, so the cp.async ring never drains and the epilogue
// overlaps the next tile's loads.
// ---------------------------------------------------------------------------
#define BK 64
#define STAGE_BYTES 32768            // A 16KB + B 16KB
#define NSTAGE 3
#define SMEM_TOTAL (NSTAGE * STAGE_BYTES)   // 98304
#define NTILES ((M_TOTAL / 128) * (N_TOTAL / 128))   // 5504

#define CP_ASYNC16(dst, src) \
    asm volatile("cp.async.cg.shared.global [%0], [%1], 16;" :: "r"(dst), "l"(src))
#define CP_COMMIT() asm volatile("cp.async.commit_group;" ::: "memory")
#define CP_WAIT(n)  asm volatile("cp.async.wait_group %0;" :: "n"(n) : "memory")

#define LDSM_X4(r0, r1, r2, r3, a)                                            \
    asm volatile("ldmatrix.sync.aligned.m8n8.x4.shared.b16 {%0,%1,%2,%3}, [%4];" \
                 : "=r"(r0), "=r"(r1), "=r"(r2), "=r"(r3) : "r"(a))

__global__ void __launch_bounds__(128, 2)
gemm_fp16_kernel(const float* __restrict__ bias, float* __restrict__ C) {
    extern __shared__ char smem[];
    uint32_t sbase;
    asm("{ .reg .u64 t; cvta.to.shared.u64 t, %1; cvt.u32.u64 %0, t; }"
        : "=r"(sbase) : "l"(smem));

    const int tid  = threadIdx.x;
    const int lane = tid & 31;
    const int warp = tid >> 5;       // 0..3
    const int wm   = warp & 1;       // 2 warps along M (64 rows each)
    const int wn   = warp >> 1;      // 2 warps along N (64 cols each)
    const int gID  = lane >> 2;
    const int t4   = lane & 3;

    const int tiles_n = N_TOTAL / 128;   // 86
    const int GRP = 16;

    // tile index -> panels (GRP-striped raster; concurrent tiles contiguous)
    auto tileMap = [&](int tile, const __half*& Ag, const __half*& Bg,
                       int& m0, int& n0) {
        int stripe = tile / (GRP * tiles_n);
        int rem = tile - stripe * (GRP * tiles_n);
        int tm = stripe * GRP + (rem % GRP);
        int tn = rem / GRP;
        m0 = tm * 128;
        n0 = tn * 128;
        Ag = g_x + (size_t)m0 * K_TOTAL;
        Bg = g_W + (size_t)n0 * K_TOTAL;
    };

    float acc[4][8][4];
#pragma unroll
    for (int i = 0; i < 4; i++)
#pragma unroll
        for (int j = 0; j < 8; j++)
#pragma unroll
            for (int k = 0; k < 4; k++) acc[i][j][k] = 0.f;

    // Per-thread cp.async addressing (128 threads: 8 A slots + 8 B slots)
    const int r0i = tid >> 3;            // 0..15
    const int ccc = tid & 7;             // chunk
    const uint32_t cdst_off = (uint32_t)r0i * 128 + (uint32_t)((ccc ^ (r0i & 7)) << 4);

    auto issueA = [&](const __half* Ag, int kt, int stage) {
        int kbase = kt * BK;
        uint32_t stg = sbase + stage * STAGE_BYTES;
#pragma unroll
        for (int t = 0; t < 8; t++) {            // A: 128 rows x 8 chunks
            uint32_t dst = stg + t * 2048 + cdst_off;
            const __half* src = Ag + (size_t)(t * 16 + r0i) * K_TOTAL + kbase + ccc * 8;
            CP_ASYNC16(dst, src);
        }
    };
    auto issueB = [&](const __half* Bg, int kt, int stage) {
        int kbase = kt * BK;
        uint32_t stg = sbase + stage * STAGE_BYTES + 16384;
#pragma unroll
        for (int t = 0; t < 8; t++) {            // B: 128 rows x 8 chunks
            uint32_t dst = stg + t * 2048 + cdst_off;
            const __half* src = Bg + (size_t)(t * 16 + r0i) * K_TOTAL + kbase + ccc * 8;
            CP_ASYNC16(dst, src);
        }
    };

    // ldmatrix per-thread row/chunk decomposition
    const int arow = (lane & 7) + ((lane >> 3) & 1) * 8;   // 0..15
    const int akp  = lane >> 4;                            // 0/1 (k half)
    const int brow = (lane & 7) + (lane >> 4) * 8;         // 0..15
    const int bkp  = (lane >> 3) & 1;                      // 0/1 (k half)
    const int l7   = lane & 7;

    const uint32_t a_row_off = (uint32_t)(wm * 64 + arow) * 128;
    const uint32_t b_row_off = 16384u + (uint32_t)(wn * 64 + brow) * 128;

    // Full double-buffered fragments (reg budget: 256/thread at 128thr x 2CTA)
    uint32_t afr[2][4][4], bfr[2][4][4];

    auto ldfragA = [&](uint32_t stg, int ks, int buf) {
#pragma unroll
        for (int mt = 0; mt < 4; mt++) {
            uint32_t addr = stg + a_row_off + (uint32_t)(mt * 16) * 128 +
                            (uint32_t)(((2 * ks + akp) ^ l7) << 4);
            LDSM_X4(afr[buf][mt][0], afr[buf][mt][1],
                    afr[buf][mt][2], afr[buf][mt][3], addr);
        }
    };
    auto ldfragB = [&](uint32_t stg, int ks, int buf) {
#pragma unroll
        for (int p = 0; p < 4; p++) {            // 4 LDSM.x4 cover 64 cols
            uint32_t addr = stg + b_row_off + (uint32_t)(p * 16) * 128 +
                            (uint32_t)(((2 * ks + bkp) ^ l7) << 4);
            LDSM_X4(bfr[buf][p][0], bfr[buf][p][1],
                    bfr[buf][p][2], bfr[buf][p][3], addr);
        }
    };

    const int NK = K_TOTAL / BK;   // 64
    int stage = 0;

    // One pipeline body == one R13 kt-iteration. pA/pB/pkt/pf select the
    // prefetch target; in the hot loop they are the current tile + pf=true
    // (const-folded), so the body is identical to R13's.
    auto body = [&](const __half* pA, const __half* pB, int pkt, bool pf) {
        CP_WAIT(1);
        __syncthreads();
        int s2 = stage + 2; if (s2 >= NSTAGE) s2 -= NSTAGE;
        uint32_t stg = sbase + stage * STAGE_BYTES;

        ldfragA(stg, 0, 0);
        ldfragB(stg, 0, 0);

#pragma unroll
        for (int ks = 0; ks < 4; ks++) {
            const int cur = ks & 1;
            const int nxt = cur ^ 1;
            if (ks < 3) { ldfragA(stg, ks + 1, nxt); ldfragB(stg, ks + 1, nxt); }
#pragma unroll
            for (int mt = 0; mt < 4; mt++)
#pragma unroll
                for (int nt = 0; nt < 8; nt++) {
                    uint32_t b0 = bfr[cur][nt >> 1][(nt & 1) * 2];
                    uint32_t b1 = bfr[cur][nt >> 1][(nt & 1) * 2 + 1];
                    asm volatile(
                        "mma.sync.aligned.m16n8k16.row.col.f32.f16.f16.f32 "
                        "{%0,%1,%2,%3}, {%4,%5,%6,%7}, {%8,%9}, {%0,%1,%2,%3};\n"
                        : "+f"(acc[mt][nt][0]), "+f"(acc[mt][nt][1]),
                          "+f"(acc[mt][nt][2]), "+f"(acc[mt][nt][3])
                        : "r"(afr[cur][mt][0]), "r"(afr[cur][mt][1]),
                          "r"(afr[cur][mt][2]), "r"(afr[cur][mt][3]),
                          "r"(b0), "r"(b1));
                }
            if (ks == 0 && pf) issueA(pA, pkt, s2);
            if (ks == 1) { if (pf) issueB(pB, pkt, s2); CP_COMMIT(); }
        }
        stage = (stage + 1 == NSTAGE) ? 0 : stage + 1;
    };

    int tile = blockIdx.x;
    const __half *Ag, *Bg;
    int m0, n0;
    tileMap(tile, Ag, Bg, m0, n0);

    issueA(Ag, 0, 0); issueB(Bg, 0, 0); CP_COMMIT();
    issueA(Ag, 1, 1); issueB(Bg, 1, 1); CP_COMMIT();

    while (true) {
        // Hot loop: identical to R13 (prefetch within current tile).
        for (int kt = 0; kt < NK - 2; kt++)
            body(Ag, Bg, kt + 2, true);

        // Peeled transitions: prefetch next tile's first two K-tiles.
        bool hasNext = (tile + (int)gridDim.x) < NTILES;
        const __half *AgN = Ag, *BgN = Bg;
        int m0n = m0, n0n = n0;
        if (hasNext) tileMap(tile + (int)gridDim.x, AgN, BgN, m0n, n0n);
        body(AgN, BgN, 0, hasNext);
        body(AgN, BgN, 1, hasNext);

        // Epilogue (no SMEM): overlaps the next tile's in-flight loads.
#pragma unroll
        for (int nt = 0; nt < 8; nt++) {
            int col = n0 + wn * 64 + nt * 8 + t4 * 2;
            float2 bv = *reinterpret_cast<const float2*>(bias + col);
#pragma unroll
            for (int mt = 0; mt < 4; mt++) {
                int row0 = m0 + wm * 64 + mt * 16 + gID;
                float2 v0 = make_float2(acc[mt][nt][0] + bv.x, acc[mt][nt][1] + bv.y);
                float2 v1 = make_float2(acc[mt][nt][2] + bv.x, acc[mt][nt][3] + bv.y);
                *reinterpret_cast<float2*>(C + (size_t)row0 * N_TOTAL + col)       = v0;
                *reinterpret_cast<float2*>(C + (size_t)(row0 + 8) * N_TOTAL + col) = v1;
                acc[mt][nt][0] = 0.f; acc[mt][nt][1] = 0.f;
                acc[mt][nt][2] = 0.f; acc[mt][nt][3] = 0.f;
            }
        }

        if (!hasNext) break;
        tile += (int)gridDim.x;
        Ag = AgN; Bg = BgN; m0 = m0n; n0 = n0n;
    }
}

// ---------------------------------------------------------------------------
// Launch. Inputs: x, W_q, scale, zero, bias. Output fp32.
// ---------------------------------------------------------------------------
extern "C" void kernel_launch(void* const* d_in, const int* in_sizes, int n_in,
                              void* d_out, int out_size) {
    const float* x     = (const float*)d_in[0];
    const int*   Wq    = (const int*)d_in[1];
    const float* scale = (const float*)d_in[2];
    const float* zero  = (const float*)d_in[3];
    const float* bias  = (const float*)d_in[4];
    float* out = (float*)d_out;

    prep_kernel<<<DQ_BLOCKS + CX_BLOCKS, 256>>>((const int4*)Wq,
                                                (const float4*)scale,
                                                (const float4*)zero,
                                                (const float4*)x);
    {
        cudaFuncSetAttribute(gemm_fp16_kernel,
                             cudaFuncAttributeMaxDynamicSharedMemorySize, SMEM_TOTAL);
        gemm_fp16_kernel<<<296, 128, SMEM_TOTAL>>>(bias, out);
    }
}

// round 16
// speedup vs baseline: 1.0951x; 1.0241x over previous
#include <cuda_runtime.h>
#include <cuda_fp16.h>
#include <cstdint>

// Problem constants
#define K_TOTAL 4096
#define N_TOTAL 11008
#define M_TOTAL 8192
#define NGROUPS 704512

// Scratch (static device globals)
__device__ __half g_W[(size_t)N_TOTAL * K_TOTAL];   // dequantized fp16, [out][in] K-major
__device__ __half g_x[(size_t)M_TOTAL * K_TOTAL];   // fp16 activations

// ---------------------------------------------------------------------------
// Kernel 1: merged prep (unchanged; near memory-bound).
// ---------------------------------------------------------------------------
#define DQ_BLOCKS 22016     // (32*NGROUPS/4) / 256
#define CX_BLOCKS 16384     // (M*K/8) / 256

__global__ void prep_kernel(const int4* __restrict__ Wq,
                            const float4* __restrict__ scale,
                            const float4* __restrict__ zero,
                            const float4* __restrict__ x) {
    int b = blockIdx.x;
    if (b < DQ_BLOCKS) {
        const int total = 32 * NGROUPS;
        int i = b * blockDim.x + threadIdx.x;    // quad index
        int base = i * 4;
        if (base >= total) return;
        int g4 = base % NGROUPS;
        int4 q = Wq[i];
        float4 s = scale[g4 >> 2];
        float4 z = zero[g4 >> 2];

        float h0 = ((float)((q.x >> 4) & 0xF) - z.x) * s.x;
        float l0 = ((float)(q.x & 0xF)        - z.x) * s.x;
        float h1 = ((float)((q.y >> 4) & 0xF) - z.y) * s.y;
        float l1 = ((float)(q.y & 0xF)        - z.y) * s.y;
        float h2 = ((float)((q.z >> 4) & 0xF) - z.z) * s.z;
        float l2 = ((float)(q.z & 0xF)        - z.z) * s.z;
        float h3 = ((float)((q.w >> 4) & 0xF) - z.w) * s.w;
        float l3 = ((float)(q.w & 0xF)        - z.w) * s.w;

        __half2 hA = __floats2half2_rn(h0, h1), hB = __floats2half2_rn(h2, h3);
        __half2 lA = __floats2half2_rn(l0, l1), lB = __floats2half2_rn(l2, l3);
        uint2 hs, ls;
        hs.x = *reinterpret_cast<uint32_t*>(&hA); hs.y = *reinterpret_cast<uint32_t*>(&hB);
        ls.x = *reinterpret_cast<uint32_t*>(&lA); ls.y = *reinterpret_cast<uint32_t*>(&lB);
        *reinterpret_cast<uint2*>(g_W + base)         = hs;
        *reinterpret_cast<uint2*>(g_W + base + total) = ls;
    } else {
        int i = (b - DQ_BLOCKS) * blockDim.x + threadIdx.x;
        const int n8 = (M_TOTAL * K_TOTAL) / 8;
        if (i >= n8) return;
        float4 v0 = x[2 * i];
        float4 v1 = x[2 * i + 1];
        __half2 a = __floats2half2_rn(v0.x, v0.y);
        __half2 bb = __floats2half2_rn(v0.z, v0.w);
        __half2 c = __floats2half2_rn(v1.x, v1.y);
        __half2 d = __floats2half2_rn(v1.z, v1.w);
        uint4 o;
        o.x = *reinterpret_cast<uint32_t*>(&a);
        o.y = *reinterpret_cast<uint32_t*>(&bb);
        o.z = *reinterpret_cast<uint32_t*>(&c);
        o.w = *reinterpret_cast<uint32_t*>(&d);
        reinterpret_cast<uint4*>(g_x)[i] = o;
    }
}

// ---------------------------------------------------------------------------
// Kernel 2: fp16 tensor-core GEMM (mma.sync m16n8k16, fp32 accum).
// EXACT R13 configuration (best measured: 1505.5us total, tensor=83.9%):
// block tile 128x128x64, 4 warps (2Mx2N, warp tile 64x64), 128 threads,
// full A+B fragment double-buffering, 3-stage cp.async ring (96KB),
// 2 CTAs/SM, cp.async interleaved into the MMA stream.
// Only change vs R13: C stores use st.global.cs (streaming, evict-first) so
// the 360MB write-only output doesn't evict A/B panels from L2; bias via ldg.
// ---------------------------------------------------------------------------
#define BK 64
#define STAGE_BYTES 32768            // A 16KB + B 16KB
#define NSTAGE 3
#define SMEM_TOTAL (NSTAGE * STAGE_BYTES)   // 98304

#define CP_ASYNC16(dst, src) \
    asm volatile("cp.async.cg.shared.global [%0], [%1], 16;" :: "r"(dst), "l"(src))
#define CP_COMMIT() asm volatile("cp.async.commit_group;" ::: "memory")
#define CP_WAIT(n)  asm volatile("cp.async.wait_group %0;" :: "n"(n) : "memory")

#define LDSM_X4(r0, r1, r2, r3, a)                                            \
    asm volatile("ldmatrix.sync.aligned.m8n8.x4.shared.b16 {%0,%1,%2,%3}, [%4];" \
                 : "=r"(r0), "=r"(r1), "=r"(r2), "=r"(r3) : "r"(a))

#define STG64_CS(ptr, v)                                                      \
    asm volatile("st.global.cs.v2.f32 [%0], {%1, %2};"                        \
                 :: "l"(ptr), "f"((v).x), "f"((v).y) : "memory")

__global__ void __launch_bounds__(128, 2)
gemm_fp16_kernel(const float* __restrict__ bias, float* __restrict__ C) {
    extern __shared__ char smem[];
    uint32_t sbase;
    asm("{ .reg .u64 t; cvta.to.shared.u64 t, %1; cvt.u32.u64 %0, t; }"
        : "=r"(sbase) : "l"(smem));

    const int tid  = threadIdx.x;
    const int lane = tid & 31;
    const int warp = tid >> 5;       // 0..3
    const int wm   = warp & 1;       // 2 warps along M (64 rows each)
    const int wn   = warp >> 1;      // 2 warps along N (64 cols each)
    const int gID  = lane >> 2;
    const int t4   = lane & 3;

    // CTA swizzle: stripes of 16 M-tiles keep B panels L2-resident.
    const int tiles_n = N_TOTAL / 128;   // 86
    const int GRP = 16;
    int gid = blockIdx.x;
    int stripe = gid / (GRP * tiles_n);
    int rem = gid - stripe * (GRP * tiles_n);
    int tm = stripe * GRP + (rem % GRP);
    int tn = rem / GRP;
    const int m0 = tm * 128;
    const int n0 = tn * 128;

    const __half* Ag = g_x + (size_t)m0 * K_TOTAL;
    const __half* Bg = g_W + (size_t)n0 * K_TOTAL;

    float acc[4][8][4];
#pragma unroll
    for (int i = 0; i < 4; i++)
#pragma unroll
        for (int j = 0; j < 8; j++)
#pragma unroll
            for (int k = 0; k < 4; k++) acc[i][j][k] = 0.f;

    // Per-thread cp.async addressing (128 threads: 8 A slots + 8 B slots)
    const int r0i = tid >> 3;            // 0..15
    const int ccc = tid & 7;             // chunk
    const uint32_t cdst_off = (uint32_t)r0i * 128 + (uint32_t)((ccc ^ (r0i & 7)) << 4);

    auto issueA = [&](int kt, int stage) {
        int kbase = kt * BK;
        uint32_t stg = sbase + stage * STAGE_BYTES;
#pragma unroll
        for (int t = 0; t < 8; t++) {            // A: 128 rows x 8 chunks
            uint32_t dst = stg + t * 2048 + cdst_off;
            const __half* src = Ag + (size_t)(t * 16 + r0i) * K_TOTAL + kbase + ccc * 8;
            CP_ASYNC16(dst, src);
        }
    };
    auto issueB = [&](int kt, int stage) {
        int kbase = kt * BK;
        uint32_t stg = sbase + stage * STAGE_BYTES + 16384;
#pragma unroll
        for (int t = 0; t < 8; t++) {            // B: 128 rows x 8 chunks
            uint32_t dst = stg + t * 2048 + cdst_off;
            const __half* src = Bg + (size_t)(t * 16 + r0i) * K_TOTAL + kbase + ccc * 8;
            CP_ASYNC16(dst, src);
        }
    };

    // ldmatrix per-thread row/chunk decomposition
    const int arow = (lane & 7) + ((lane >> 3) & 1) * 8;   // 0..15
    const int akp  = lane >> 4;                            // 0/1 (k half)
    const int brow = (lane & 7) + (lane >> 4) * 8;         // 0..15
    const int bkp  = (lane >> 3) & 1;                      // 0/1 (k half)
    const int l7   = lane & 7;

    const uint32_t a_row_off = (uint32_t)(wm * 64 + arow) * 128;
    const uint32_t b_row_off = 16384u + (uint32_t)(wn * 64 + brow) * 128;

    // Full double-buffered fragments (reg budget: 256/thread at 128thr x 2CTA)
    uint32_t afr[2][4][4], bfr[2][4][4];

    auto ldfragA = [&](uint32_t stg, int ks, int buf) {
#pragma unroll
        for (int mt = 0; mt < 4; mt++) {
            uint32_t addr = stg + a_row_off + (uint32_t)(mt * 16) * 128 +
                            (uint32_t)(((2 * ks + akp) ^ l7) << 4);
            LDSM_X4(afr[buf][mt][0], afr[buf][mt][1],
                    afr[buf][mt][2], afr[buf][mt][3], addr);
        }
    };
    auto ldfragB = [&](uint32_t stg, int ks, int buf) {
#pragma unroll
        for (int p = 0; p < 4; p++) {            // 4 LDSM.x4 cover 64 cols
            uint32_t addr = stg + b_row_off + (uint32_t)(p * 16) * 128 +
                            (uint32_t)(((2 * ks + bkp) ^ l7) << 4);
            LDSM_X4(bfr[buf][p][0], bfr[buf][p][1],
                    bfr[buf][p][2], bfr[buf][p][3], addr);
        }
    };

    const int NK = K_TOTAL / BK;   // 64

    issueA(0, 0); issueB(0, 0); CP_COMMIT();
    issueA(1, 1); issueB(1, 1); CP_COMMIT();

    int stage = 0;
    for (int kt = 0; kt < NK; kt++) {
        CP_WAIT(1);
        __syncthreads();
        int s2 = stage + 2; if (s2 >= NSTAGE) s2 -= NSTAGE;
        const bool pf = (kt + 2 < NK);
        uint32_t stg = sbase + stage * STAGE_BYTES;

        // Prime ks=0 fragments (only exposed LDS latency in the stage).
        ldfragA(stg, 0, 0);
        ldfragB(stg, 0, 0);

#pragma unroll
        for (int ks = 0; ks < 4; ks++) {
            const int cur = ks & 1;
            const int nxt = cur ^ 1;
            // Next sub-step's fragments: latency hides under 32 MMAs.
            if (ks < 3) { ldfragA(stg, ks + 1, nxt); ldfragB(stg, ks + 1, nxt); }
#pragma unroll
            for (int mt = 0; mt < 4; mt++)
#pragma unroll
                for (int nt = 0; nt < 8; nt++) {
                    uint32_t b0 = bfr[cur][nt >> 1][(nt & 1) * 2];
                    uint32_t b1 = bfr[cur][nt >> 1][(nt & 1) * 2 + 1];
                    asm volatile(
                        "mma.sync.aligned.m16n8k16.row.col.f32.f16.f16.f32 "
                        "{%0,%1,%2,%3}, {%4,%5,%6,%7}, {%8,%9}, {%0,%1,%2,%3};\n"
                        : "+f"(acc[mt][nt][0]), "+f"(acc[mt][nt][1]),
                          "+f"(acc[mt][nt][2]), "+f"(acc[mt][nt][3])
                        : "r"(afr[cur][mt][0]), "r"(afr[cur][mt][1]),
                          "r"(afr[cur][mt][2]), "r"(afr[cur][mt][3]),
                          "r"(b0), "r"(b1));
                }
            // Interleave next-stage global prefetch into the MMA stream.
            if (ks == 0 && pf) issueA(kt + 2, s2);
            if (ks == 1) { if (pf) issueB(kt + 2, s2); CP_COMMIT(); }
        }
        stage = (stage + 1 == NSTAGE) ? 0 : stage + 1;
    }

    // Epilogue: bias add + streaming fp32 stores (evict-first; C never reread)
    float2 bv[8];
#pragma unroll
    for (int nt = 0; nt < 8; nt++) {
        int col = n0 + wn * 64 + nt * 8 + t4 * 2;
        bv[nt].x = __ldg(bias + col);
        bv[nt].y = __ldg(bias + col + 1);
    }
#pragma unroll
    for (int mt = 0; mt < 4; mt++) {
#pragma unroll
        for (int nt = 0; nt < 8; nt++) {
            int row0 = m0 + wm * 64 + mt * 16 + gID;
            int col  = n0 + wn * 64 + nt * 8 + t4 * 2;
            float2 v0 = make_float2(acc[mt][nt][0] + bv[nt].x, acc[mt][nt][1] + bv[nt].y);
            float2 v1 = make_float2(acc[mt][nt][2] + bv[nt].x, acc[mt][nt][3] + bv[nt].y);
            STG64_CS(C + (size_t)row0 * N_TOTAL + col, v0);
            STG64_CS(C + (size_t)(row0 + 8) * N_TOTAL + col, v1);
        }
    }
}

// ---------------------------------------------------------------------------
// Launch. Inputs: x, W_q, scale, zero, bias. Output fp32.
// ---------------------------------------------------------------------------
extern "C" void kernel_launch(void* const* d_in, const int* in_sizes, int n_in,
                              void* d_out, int out_size) {
    const float* x     = (const float*)d_in[0];
    const int*   Wq    = (const int*)d_in[1];
    const float* scale = (const float*)d_in[2];
    const float* zero  = (const float*)d_in[3];
    const float* bias  = (const float*)d_in[4];
    float* out = (float*)d_out;

    prep_kernel<<<DQ_BLOCKS + CX_BLOCKS, 256>>>((const int4*)Wq,
                                                (const float4*)scale,
                                                (const float4*)zero,
                                                (const float4*)x);
    {
        cudaFuncSetAttribute(gemm_fp16_kernel,
                             cudaFuncAttributeMaxDynamicSharedMemorySize, SMEM_TOTAL);
        int blocks = (M_TOTAL / 128) * (N_TOTAL / 128);   // 5504
        gemm_fp16_kernel<<<blocks, 128, SMEM_TOTAL>>>(bias, out);
    }
}